// round 5
// baseline (speedup 1.0000x reference)
#include <cuda_runtime.h>
#include <cstddef>

// Problem constants
#define B_   8192
#define T_   2048
#define H_   51
#define HP   52            // padded hidden
#define GP   208           // 4*HP padded gates
#define BB   64            // batch rows per block
#define NTH  256           // threads per block
#define NBLK (B_ / BB)     // 128 blocks

// Shared memory layout (float offsets)
#define OFF_W1   0                         // [HP][GP]   h1 -> gates1 weights (k-major)
#define OFF_W2   (OFF_W1 + HP * GP)        // [2*HP][GP] [h1;h2] -> gates2 weights
#define OFF_WX   (OFF_W2 + 2 * HP * GP)    // [GP]       x -> gates1 weights (W_ih1 col)
#define OFF_BS1  (OFF_WX + GP)             // [GP]       b_ih1 + b_hh1
#define OFF_BS2  (OFF_BS1 + GP)            // [GP]       b_ih2 + b_hh2
#define OFF_WLIN (OFF_BS2 + GP)            // [64]       output linear weights (padded)
#define OFF_XS   (OFF_WLIN + 64)           // [64]       staged x_t for this block
#define OFF_HCAT (OFF_XS + 64)             // [2*HP][BB] h1 rows 0..51, h2 rows 52..103
#define OFF_GSM  (OFF_HCAT + 2 * HP * BB)  // [GP][BB]   gate pre-activations
#define SMEM_FLOATS (OFF_GSM + GP * BB)
#define SMEM_BYTES  (SMEM_FLOATS * (int)sizeof(float))   // ~212.7 KB

__device__ __forceinline__ float sigf(float v) {
    // accurate fast sigmoid: 1/(1+e^-v) via MUFU.EX2 + MUFU.RCP (~1e-7 err)
    return __fdividef(1.0f, 1.0f + __expf(-v));
}
__device__ __forceinline__ float tanhfast(float v) {
    // tanh(v) = 2/(1+e^-2v) - 1 ; exact at extremes, ~1e-7 abs err
    return __fdividef(2.0f, 1.0f + __expf(-2.0f * v)) - 1.0f;
}

// Register-tiled GEMM: acc[4 batch][13 gate-cols] += hcat(K x 64) * W(K x 208)
template <int K>
__device__ __forceinline__ void gemm_tile(const float* __restrict__ W,
                                          const float* __restrict__ hc,
                                          int b0, int j0,
                                          float a0[13], float a1[13],
                                          float a2[13], float a3[13]) {
#pragma unroll
    for (int c = 0; c < 13; c++) { a0[c] = 0.f; a1[c] = 0.f; a2[c] = 0.f; a3[c] = 0.f; }
#pragma unroll 4
    for (int k = 0; k < K; k++) {
        float4 hv = *reinterpret_cast<const float4*>(hc + k * BB + b0);
        const float* wr = W + k * GP + j0;
#pragma unroll
        for (int c = 0; c < 13; c++) {
            float w = wr[c];
            a0[c] = fmaf(hv.x, w, a0[c]);
            a1[c] = fmaf(hv.y, w, a1[c]);
            a2[c] = fmaf(hv.z, w, a2[c]);
            a3[c] = fmaf(hv.w, w, a3[c]);
        }
    }
}

extern __shared__ float smf[];

__global__ __launch_bounds__(NTH, 1)
void lstm_rnn_kernel(const float* __restrict__ x,
                     const float* __restrict__ Wih1, const float* __restrict__ Whh1,
                     const float* __restrict__ bih1, const float* __restrict__ bhh1,
                     const float* __restrict__ Wih2, const float* __restrict__ Whh2,
                     const float* __restrict__ bih2, const float* __restrict__ bhh2,
                     const float* __restrict__ Wlin, const float* __restrict__ blin_p,
                     float* __restrict__ out) {
    float* W1   = smf + OFF_W1;
    float* W2   = smf + OFF_W2;
    float* wx   = smf + OFF_WX;
    float* bs1  = smf + OFF_BS1;
    float* bs2  = smf + OFF_BS2;
    float* wlin = smf + OFF_WLIN;
    float* xs   = smf + OFF_XS;
    float* hcat = smf + OFF_HCAT;
    float* gsm  = smf + OFF_GSM;

    const int t     = threadIdx.x;
    const int bbase = blockIdx.x * BB;

    // ---- one-time (per launch) init: transpose + pad weights into SMEM ----
    for (int idx = t; idx < HP * GP; idx += NTH) {
        int k = idx / GP, gp = idx % GP;
        int g = gp / HP, j = gp % HP;
        W1[idx] = (j < H_ && k < H_) ? Whh1[(g * H_ + j) * H_ + k] : 0.f;
    }
    for (int idx = t; idx < 2 * HP * GP; idx += NTH) {
        int k = idx / GP, gp = idx % GP;
        int g = gp / HP, j = gp % HP;
        float v = 0.f;
        if (j < H_) {
            if (k < H_)                      v = Wih2[(g * H_ + j) * H_ + k];
            else if (k >= HP && k < HP + H_) v = Whh2[(g * H_ + j) * H_ + (k - HP)];
        }
        W2[idx] = v;
    }
    for (int gp = t; gp < GP; gp += NTH) {
        int g = gp / HP, j = gp % HP;
        if (j < H_) {
            wx[gp]  = Wih1[g * H_ + j];                          // W_ih1 is [4H,1]
            bs1[gp] = bih1[g * H_ + j] + bhh1[g * H_ + j];
            bs2[gp] = bih2[g * H_ + j] + bhh2[g * H_ + j];
        } else {
            wx[gp] = 0.f; bs1[gp] = 0.f; bs2[gp] = 0.f;
        }
    }
    if (t < 64) wlin[t] = (t < H_) ? Wlin[t] : 0.f;
    for (int idx = t; idx < 2 * HP * BB; idx += NTH) hcat[idx] = 0.f;
    const float blin = blin_p[0];

    // GEMM tile coordinates
    const int b0 = (t & 15) * 4;   // batch rows b0..b0+3
    const int j0 = (t >> 4) * 13;  // gate cols j0..j0+12
    // Elementwise coordinates: thread owns batch row `be`, j = jb + 4i
    const int be = t & 63;
    const int jb = t >> 6;

    float c1r[13], c2r[13];
#pragma unroll
    for (int i = 0; i < 13; i++) { c1r[i] = 0.f; c2r[i] = 0.f; }

    float xnext = (t < BB) ? x[(size_t)(bbase + t) * T_] : 0.f;

    __syncthreads();

    for (int step = 0; step < T_; ++step) {
        if (t < BB) xs[t] = xnext;
        __syncthreads();
        if (t < BB && step + 1 < T_)
            xnext = __ldg(&x[(size_t)(bbase + t) * T_ + step + 1]);  // prefetch, hidden by GEMM

        // ---- layer-1 GEMM: gates1 = h1 @ Whh1^T (+ x*wx + b) ----
        {
            float a0[13], a1[13], a2[13], a3[13];
            gemm_tile<HP>(W1, hcat, b0, j0, a0, a1, a2, a3);
            float4 xv = *reinterpret_cast<const float4*>(&xs[b0]);
#pragma unroll
            for (int c = 0; c < 13; c++) {
                int gp = j0 + c;
                float wxx = wx[gp], bb = bs1[gp];
                float4 o;
                o.x = fmaf(xv.x, wxx, a0[c] + bb);
                o.y = fmaf(xv.y, wxx, a1[c] + bb);
                o.z = fmaf(xv.z, wxx, a2[c] + bb);
                o.w = fmaf(xv.w, wxx, a3[c] + bb);
                *reinterpret_cast<float4*>(&gsm[gp * BB + b0]) = o;
            }
        }
        __syncthreads();

        // ---- layer-1 elementwise: c1,h1 update (h1 -> hcat rows 0..51) ----
#pragma unroll
        for (int i = 0; i < 13; i++) {
            int j = jb + 4 * i;
            float ig = gsm[(0 * HP + j) * BB + be];
            float fg = gsm[(1 * HP + j) * BB + be];
            float gg = gsm[(2 * HP + j) * BB + be];
            float og = gsm[(3 * HP + j) * BB + be];
            float ia = sigf(ig), fa = sigf(fg), ga = tanhfast(gg), oa = sigf(og);
            float c = fmaf(fa, c1r[i], ia * ga);
            c1r[i] = c;
            hcat[j * BB + be] = oa * tanhfast(c);
        }
        __syncthreads();

        // ---- layer-2 GEMM: gates2 = [h1;h2] @ [Wih2;Whh2]^T (+ b) ----
        {
            float a0[13], a1[13], a2[13], a3[13];
            gemm_tile<2 * HP>(W2, hcat, b0, j0, a0, a1, a2, a3);
#pragma unroll
            for (int c = 0; c < 13; c++) {
                int gp = j0 + c;
                float bb = bs2[gp];
                float4 o;
                o.x = a0[c] + bb;
                o.y = a1[c] + bb;
                o.z = a2[c] + bb;
                o.w = a3[c] + bb;
                *reinterpret_cast<float4*>(&gsm[gp * BB + b0]) = o;
            }
        }
        __syncthreads();

        // ---- layer-2 elementwise: c2,h2 update (h2 -> hcat rows 52..103) ----
#pragma unroll
        for (int i = 0; i < 13; i++) {
            int j = jb + 4 * i;
            float ig = gsm[(0 * HP + j) * BB + be];
            float fg = gsm[(1 * HP + j) * BB + be];
            float gg = gsm[(2 * HP + j) * BB + be];
            float og = gsm[(3 * HP + j) * BB + be];
            float ia = sigf(ig), fa = sigf(fg), ga = tanhfast(gg), oa = sigf(og);
            float c = fmaf(fa, c2r[i], ia * ga);
            c2r[i] = c;
            hcat[(HP + j) * BB + be] = oa * tanhfast(c);
        }
        __syncthreads();

        // ---- output projection: y[b] = h2 . Wlin + blin ----
        if (t < BB) {
            float y = blin;
#pragma unroll
            for (int j = 0; j < H_; j++)
                y = fmaf(hcat[(HP + j) * BB + t], wlin[j], y);
            out[(size_t)(bbase + t) * T_ + step] = y;
        }
        // loop-top __syncthreads() separates this read/write from next GEMM1
    }
}

extern "C" void kernel_launch(void* const* d_in, const int* in_sizes, int n_in,
                              void* d_out, int out_size) {
    (void)in_sizes; (void)n_in; (void)out_size;
    const float* x    = (const float*)d_in[0];
    const float* Wih1 = (const float*)d_in[1];
    const float* Whh1 = (const float*)d_in[2];
    const float* bih1 = (const float*)d_in[3];
    const float* bhh1 = (const float*)d_in[4];
    const float* Wih2 = (const float*)d_in[5];
    const float* Whh2 = (const float*)d_in[6];
    const float* bih2 = (const float*)d_in[7];
    const float* bhh2 = (const float*)d_in[8];
    const float* Wlin = (const float*)d_in[9];
    const float* blin = (const float*)d_in[10];
    float* out = (float*)d_out;

    cudaFuncSetAttribute(lstm_rnn_kernel,
                         cudaFuncAttributeMaxDynamicSharedMemorySize, SMEM_BYTES);

    lstm_rnn_kernel<<<NBLK, NTH, SMEM_BYTES>>>(x, Wih1, Whh1, bih1, bhh1,
                                               Wih2, Whh2, bih2, bhh2,
                                               Wlin, blin, out);
}